// round 16
// baseline (speedup 1.0000x reference)
#include <cuda_runtime.h>

// SuperVoxelLoss: mean( bce_with_logits(x,t) * (1 + 0.5*[(t>0.5) XOR (x>0)]) )
// R11 bench-best memory config (occ 6, tiered L2: t + first 1/4 of x protected)
// + compute thinning: log1p(exp(-|x|)) via EX2 + degree-4 polynomial
// (Chebyshev-derived, |err| < 1e-4) -> 1 MUFU/elem instead of 2, ~13 issues.

#define NTHR 256
#define NBLK 888          // 148 SMs * 6 resident CTAs = exactly one wave

__device__ float g_partials[NBLK];
__device__ unsigned int g_ticket;   // zero-init; last block resets for graph replay

__device__ __forceinline__ float loss_elem(float x, float t) {
    // e = exp(-|x|) in (0,1]; single MUFU (EX2) after FMUL by -log2(e)
    float e = __expf(-fabsf(x));
    // log1p(e) on e in [0,1]: s = 2e-1, degree-4 poly from Chebyshev series of
    // ln((3+s)/2) with rho = 3-2*sqrt(2). Max abs err ~8e-5.
    float s = fmaf(2.0f, e, -1.0f);
    float p = fmaf(s, -0.0034663f, 0.0134684f);
    p = fmaf(s, p, -0.0554082f);
    p = fmaf(s, p, 0.3330445f);
    p = fmaf(s, p, 0.4054570f);
    // max(x,0) - x*t = x * (px - t), px = (x>0)
    bool px = x > 0.0f;
    bool pt = t > 0.5f;
    float d = (px ? 1.0f : 0.0f) - t;
    float loss = fmaf(x, d, p);
    float w = (px != pt) ? 1.5f : 1.0f;   // masks are XOR of the two bins
    return loss * w;
}

__device__ __forceinline__ float block_reduce(float v) {
    #pragma unroll
    for (int o = 16; o > 0; o >>= 1)
        v += __shfl_down_sync(0xFFFFFFFFu, v, o);

    __shared__ float s_warp[NTHR / 32];
    if ((threadIdx.x & 31) == 0) s_warp[threadIdx.x >> 5] = v;
    __syncthreads();

    if (threadIdx.x < 32) {
        float w = (threadIdx.x < NTHR / 32) ? s_warp[threadIdx.x] : 0.0f;
        #pragma unroll
        for (int o = 16; o > 0; o >>= 1)
            w += __shfl_down_sync(0xFFFFFFFFu, w, o);
        return w;   // valid in thread 0
    }
    return 0.0f;
}

__global__ void __launch_bounds__(NTHR, 6)
svloss_fused_kernel(const float4* __restrict__ x4,
                    const float4* __restrict__ t4,
                    float* __restrict__ out,
                    int n4, int x_cut, float inv_n) {
    const int stride = NBLK * NTHR;
    const int tid = blockIdx.x * NTHR + threadIdx.x;

    float a0 = 0.0f, a1 = 0.0f, a2 = 0.0f, a3 = 0.0f;

    #pragma unroll 4
    for (int i = tid; i < n4; i += stride) {
        float4 xv = (i < x_cut) ? __ldcg(&x4[i])   // protected head of x (16 MB)
                                : __ldcs(&x4[i]);  // streamed tail of x
        float4 tv = __ldcg(&t4[i]);                // t always protected (64 MB)
        a0 += loss_elem(xv.x, tv.x);
        a1 += loss_elem(xv.y, tv.y);
        a2 += loss_elem(xv.z, tv.z);
        a3 += loss_elem(xv.w, tv.w);
    }

    float bsum = block_reduce((a0 + a1) + (a2 + a3));

    __shared__ bool s_last;
    if (threadIdx.x == 0) {
        g_partials[blockIdx.x] = bsum;
        __threadfence();
        unsigned int c = atomicAdd(&g_ticket, 1u);
        s_last = (c == (unsigned int)gridDim.x - 1u);
    }
    __syncthreads();

    if (s_last) {
        // deterministic fixed-order reduce of all partials
        float v = 0.0f;
        for (int i = threadIdx.x; i < NBLK; i += NTHR)
            v += g_partials[i];
        float total = block_reduce(v);
        if (threadIdx.x == 0) {
            out[0] = total * inv_n;
            g_ticket = 0u;   // reset for next graph replay
        }
    }
}

extern "C" void kernel_launch(void* const* d_in, const int* in_sizes, int n_in,
                              void* d_out, int out_size) {
    const float4* x4 = (const float4*)d_in[0];
    const float4* t4 = (const float4*)d_in[1];
    float* out = (float*)d_out;

    int n = in_sizes[0];          // 16,777,216
    int n4 = n >> 2;              // 4,194,304 float4s per array (64 MB)
    int x_cut = n4 >> 2;          // first 16 MB of x protected

    svloss_fused_kernel<<<NBLK, NTHR>>>(x4, t4, out, n4, x_cut, 1.0f / (float)n);
}

// round 17
// speedup vs baseline: 1.0933x; 1.0933x over previous
#include <cuda_runtime.h>

// SuperVoxelLoss: mean( bce_with_logits(x,t) * (1 + 0.5*[(t>0.5) XOR (x>0)]) )
// R11 bench-best memory config (occ 6, tiered L2: t + first 1/4 of x protected)
// + issue-thinned math (~12 issues/elem, 2 MUFU):
//   - ln2 multiply folded into FFMA
//   - criticality via sign of x*(t-0.5) + predicated dual accumulation
//     (total = sum_loss + 0.5 * sum_crit_loss  ==  sum loss*w, w in {1,1.5})

#define NTHR 256
#define NBLK 888          // 148 SMs * 6 resident CTAs = exactly one wave

__device__ float g_partials[NBLK];
__device__ unsigned int g_ticket;   // zero-init; last block resets for graph replay

// Accumulate loss into a (always) and c (only when critical).
__device__ __forceinline__ void loss_acc(float x, float t, float& a, float& c) {
    float e  = __expf(-fabsf(x));                 // FMUL(|x|*-L2E) + MUFU.EX2
    float lg = __log2f(1.0f + e);                 // FADD + MUFU.LG2
    float u  = fmaf(x, -t, fmaxf(x, 0.0f));       // FMNMX + FFMA
    float loss = fmaf(lg, 0.6931471805599453f, u);// FFMA  (log1p term * ln2)
    // critical (split/merge mistake) <=> (x>0) XOR (t>0.5) <=> x*(t-0.5) < 0
    bool crit = x * (t - 0.5f) < 0.0f;            // FADD + FMUL + FSETP
    a += loss;                                    // FADD
    if (crit) c += loss;                          // @p FADD
}

__device__ __forceinline__ float block_reduce(float v) {
    #pragma unroll
    for (int o = 16; o > 0; o >>= 1)
        v += __shfl_down_sync(0xFFFFFFFFu, v, o);

    __shared__ float s_warp[NTHR / 32];
    if ((threadIdx.x & 31) == 0) s_warp[threadIdx.x >> 5] = v;
    __syncthreads();

    if (threadIdx.x < 32) {
        float w = (threadIdx.x < NTHR / 32) ? s_warp[threadIdx.x] : 0.0f;
        #pragma unroll
        for (int o = 16; o > 0; o >>= 1)
            w += __shfl_down_sync(0xFFFFFFFFu, w, o);
        return w;   // valid in thread 0
    }
    return 0.0f;
}

__global__ void __launch_bounds__(NTHR, 6)
svloss_fused_kernel(const float4* __restrict__ x4,
                    const float4* __restrict__ t4,
                    float* __restrict__ out,
                    int n4, int x_cut, float inv_n) {
    const int stride = NBLK * NTHR;
    const int tid = blockIdx.x * NTHR + threadIdx.x;

    float a0 = 0.0f, a1 = 0.0f;   // plain loss sums
    float c0 = 0.0f, c1 = 0.0f;   // critical-only loss sums

    #pragma unroll 4
    for (int i = tid; i < n4; i += stride) {
        float4 xv = (i < x_cut) ? __ldcg(&x4[i])   // protected head of x (16 MB)
                                : __ldcs(&x4[i]);  // streamed tail of x
        float4 tv = __ldcg(&t4[i]);                // t always protected (64 MB)
        loss_acc(xv.x, tv.x, a0, c0);
        loss_acc(xv.y, tv.y, a1, c1);
        loss_acc(xv.z, tv.z, a0, c0);
        loss_acc(xv.w, tv.w, a1, c1);
    }

    // weight 1.5 on critical elems == + 0.5 * critical sum
    float acc = fmaf(0.5f, c0 + c1, a0 + a1);
    float bsum = block_reduce(acc);

    __shared__ bool s_last;
    if (threadIdx.x == 0) {
        g_partials[blockIdx.x] = bsum;
        __threadfence();
        unsigned int c = atomicAdd(&g_ticket, 1u);
        s_last = (c == (unsigned int)gridDim.x - 1u);
    }
    __syncthreads();

    if (s_last) {
        // deterministic fixed-order reduce of all partials
        float v = 0.0f;
        for (int i = threadIdx.x; i < NBLK; i += NTHR)
            v += g_partials[i];
        float total = block_reduce(v);
        if (threadIdx.x == 0) {
            out[0] = total * inv_n;
            g_ticket = 0u;   // reset for next graph replay
        }
    }
}

extern "C" void kernel_launch(void* const* d_in, const int* in_sizes, int n_in,
                              void* d_out, int out_size) {
    const float4* x4 = (const float4*)d_in[0];
    const float4* t4 = (const float4*)d_in[1];
    float* out = (float*)d_out;

    int n = in_sizes[0];          // 16,777,216
    int n4 = n >> 2;              // 4,194,304 float4s per array (64 MB)
    int x_cut = n4 >> 2;          // first 16 MB of x protected

    svloss_fused_kernel<<<NBLK, NTHR>>>(x4, t4, out, n4, x_cut, 1.0f / (float)n);
}